// round 14
// baseline (speedup 1.0000x reference)
#include <cuda_runtime.h>
#include <cuda_bf16.h>
#include <math.h>
#include <stdint.h>

#define NROWS 8192
#define KC    8192
#define DD    256
#define TOTAL_Q (NROWS*DD)
#define CAND  128
#define WWIN  32.0f          // candidate logit window (>= 2*E_hard)
#define NBLK  1024           // stats blocks (NROWS/SROWS)

// ---------------- scratch ----------------
__device__ __nv_bfloat16 g_L[(size_t)NROWS * KC];    // 128 MB: bf16 logits
__device__ __nv_bfloat16 g_A[(size_t)NROWS * DD];
__device__ __nv_bfloat16 g_B[(size_t)KC * DD];
__device__ float g_avgp_p[NBLK][KC];                 // 32 MB: per-block avgp partials
__device__ float g_c2[KC];
__device__ int   g_ccnt[NROWS];
__device__ int   g_cand[(size_t)NROWS * CAND];
__device__ float g_plogp;
__device__ float g_avgent;
__device__ float g_mse;

__device__ __forceinline__ float bf2f(uint32_t lo16) {
    uint32_t u = lo16 << 16;
    return __uint_as_float(u);
}
__device__ __forceinline__ uint32_t pack2(float a, float b) {
    __nv_bfloat162 t = __floats2bfloat162_rn(a, b);
    return reinterpret_cast<uint32_t&>(t);
}

// ---------------- init ----------------
__global__ void init_kernel() {
    if (blockIdx.x == 0 && threadIdx.x == 0) { g_plogp = 0.f; g_avgent = 0.f; g_mse = 0.f; }
}

// ---------------- |c_k|^2 ----------------
__global__ __launch_bounds__(256) void c2_kernel(const float* __restrict__ cb) {
    int k = blockIdx.x;
    float v = cb[(size_t)k * DD + threadIdx.x];
    float sq = v * v;
    #pragma unroll
    for (int o = 16; o; o >>= 1) sq += __shfl_down_sync(0xffffffff, sq, o);
    __shared__ float sh[8];
    int wid = threadIdx.x >> 5, lid = threadIdx.x & 31;
    if (lid == 0) sh[wid] = sq;
    __syncthreads();
    if (threadIdx.x == 0) {
        float t = 0.f;
        #pragma unroll
        for (int w = 0; w < 8; w++) t += sh[w];
        g_c2[k] = t;
    }
}

// ---------------- fp32 -> bf16 ----------------
__global__ __launch_bounds__(256) void convert_kernel(const float* __restrict__ x,
                                                      const float* __restrict__ cb) {
    int i = (blockIdx.x * 256 + threadIdx.x) * 4;
    {
        float4 v = *(const float4*)(x + i);
        *(uint2*)(g_A + i) = make_uint2(pack2(v.x, v.y), pack2(v.z, v.w));
    }
    {
        float4 v = *(const float4*)(cb + i);
        *(uint2*)(g_B + i) = make_uint2(pack2(v.x, v.y), pack2(v.z, v.w));
    }
}

// ---------------- bf16 mma GEMM: 128x128 tile, 64x32 warps, 4-stage, 2 CTAs/SM ----------------
#define BM 128
#define BN 128
#define BK 32
#define PAD 40
#define TILE_E (128*PAD)
#define TILE_B (TILE_E*2)      // 10240 bytes
#define STAGE_B (TILE_B*2)     // 20480 bytes
#define NSTAGE 4
#define GSMEM (NSTAGE*STAGE_B) // 81920
#define NIT (DD/BK)            // 8

__device__ __forceinline__ void mma16816(float* d, const uint32_t* a, const uint32_t* b) {
    asm volatile("mma.sync.aligned.m16n8k16.row.col.f32.bf16.bf16.f32 "
        "{%0,%1,%2,%3}, {%4,%5,%6,%7}, {%8,%9}, {%0,%1,%2,%3};"
        : "+f"(d[0]), "+f"(d[1]), "+f"(d[2]), "+f"(d[3])
        : "r"(a[0]), "r"(a[1]), "r"(a[2]), "r"(a[3]), "r"(b[0]), "r"(b[1]));
}
__device__ __forceinline__ void ldsm4(uint32_t* r, uint32_t addr) {
    asm volatile("ldmatrix.sync.aligned.m8n8.x4.shared.b16 {%0,%1,%2,%3}, [%4];"
        : "=r"(r[0]), "=r"(r[1]), "=r"(r[2]), "=r"(r[3]) : "r"(addr));
}

__global__ __launch_bounds__(256, 2) void mma_gemm_kernel() {
    extern __shared__ __align__(16) char dsm[];
    int tid = threadIdx.x, lane = tid & 31, wid = tid >> 5;
    int warpM = wid & 1, warpN = wid >> 1;       // 2 x 4 warps, each 64x32
    int row0 = blockIdx.y * BM, col0 = blockIdx.x * BN;

    const __nv_bfloat16* Ag = g_A + (size_t)row0 * DD;
    const __nv_bfloat16* Bg = g_B + (size_t)col0 * DD;
    uint32_t sbase = (uint32_t)__cvta_generic_to_shared(dsm);

    int lr0 = (tid + 0)   >> 2, ls0 = (tid + 0)   & 3;
    int lr1 = (tid + 256) >> 2, ls1 = (tid + 256) & 3;
    uint32_t so0 = (uint32_t)(lr0 * PAD + ls0 * 8) * 2;
    uint32_t so1 = (uint32_t)(lr1 * PAD + ls1 * 8) * 2;

    // cp.async.cg: L2-only, keep L1TEX bandwidth for ldmatrix
    #define LOAD_STAGE(stage, kc) do { \
        uint32_t ab = sbase + (stage) * STAGE_B; \
        uint32_t bb = ab + TILE_B; \
        asm volatile("cp.async.cg.shared.global [%0], [%1], 16;" :: "r"(ab + so0), "l"(Ag + (size_t)lr0 * DD + (kc) + ls0 * 8)); \
        asm volatile("cp.async.cg.shared.global [%0], [%1], 16;" :: "r"(ab + so1), "l"(Ag + (size_t)lr1 * DD + (kc) + ls1 * 8)); \
        asm volatile("cp.async.cg.shared.global [%0], [%1], 16;" :: "r"(bb + so0), "l"(Bg + (size_t)lr0 * DD + (kc) + ls0 * 8)); \
        asm volatile("cp.async.cg.shared.global [%0], [%1], 16;" :: "r"(bb + so1), "l"(Bg + (size_t)lr1 * DD + (kc) + ls1 * 8)); \
        asm volatile("cp.async.commit_group;"); \
    } while (0)

    int lrow = ((lane >> 3) & 1) * 8 + (lane & 7);
    int lkof = (lane >> 4) * 8;
    uint32_t aoff = (uint32_t)((warpM * 64 + lrow) * PAD + lkof) * 2;
    uint32_t boff = (uint32_t)((warpN * 32 + lrow) * PAD + lkof) * 2;

    float acc[4][4][4];
    #pragma unroll
    for (int mt = 0; mt < 4; mt++)
        #pragma unroll
        for (int nt = 0; nt < 4; nt++)
            #pragma unroll
            for (int j = 0; j < 4; j++) acc[mt][nt][j] = 0.f;

    LOAD_STAGE(0, 0);
    LOAD_STAGE(1, BK);
    LOAD_STAGE(2, 2 * BK);

    int stage = 0;
    for (int it = 0; it < NIT; it++) {
        asm volatile("cp.async.wait_group 2;");
        __syncthreads();

        uint32_t bufA = sbase + stage * STAGE_B;
        uint32_t bufB = bufA + TILE_B;
        #pragma unroll
        for (int ks = 0; ks < 2; ks++) {
            uint32_t kst = ks * 16 * 2;
            uint32_t aF[4][4];
            #pragma unroll
            for (int mt = 0; mt < 4; mt++)
                ldsm4(aF[mt], bufA + aoff + mt * (16 * PAD * 2) + kst);
            uint32_t bF[4][2];
            #pragma unroll
            for (int p = 0; p < 2; p++) {
                uint32_t r[4];
                ldsm4(r, bufB + boff + p * (16 * PAD * 2) + kst);
                bF[2*p][0] = r[0]; bF[2*p][1] = r[2];
                bF[2*p+1][0] = r[1]; bF[2*p+1][1] = r[3];
            }
            #pragma unroll
            for (int mt = 0; mt < 4; mt++)
                #pragma unroll
                for (int nt = 0; nt < 4; nt++)
                    mma16816(acc[mt][nt], aF[mt], bF[nt]);
        }

        if (it + 3 < NIT) {
            int ns = (stage + 3) % NSTAGE;
            LOAD_STAGE(ns, (it + 3) * BK);
        } else {
            asm volatile("cp.async.commit_group;");
        }
        stage = (stage + 1) % NSTAGE;
    }

    // epilogue: logit = 200*G - 100*c2, store bf16
    int mr = row0 + warpM * 64 + (lane >> 2);
    int nc = col0 + warpN * 32 + (lane & 3) * 2;
    #pragma unroll
    for (int nt = 0; nt < 4; nt++) {
        int c = nc + nt * 8;
        float c2a = g_c2[c] * 100.f, c2b = g_c2[c + 1] * 100.f;
        #pragma unroll
        for (int mt = 0; mt < 4; mt++) {
            float* d = acc[mt][nt];
            size_t o0 = ((size_t)(mr + mt * 16) * KC + c) >> 1;
            size_t o1 = ((size_t)(mr + mt * 16 + 8) * KC + c) >> 1;
            ((uint32_t*)g_L)[o0] = pack2(d[0] * 200.f - c2a, d[1] * 200.f - c2b);
            ((uint32_t*)g_L)[o1] = pack2(d[2] * 200.f - c2a, d[3] * 200.f - c2b);
        }
    }
}

// ---------------- register-resident stats, row-prefetch, atomic-free avgp ----------------
// ap swizzle: logical k stored at (k&7)*1024 + (k>>3) — thread-private (all ≡ tid mod 256)
#define SROWS 8
__global__ __launch_bounds__(256) void stats_kernel() {
    __shared__ float ap[KC];          // 32 KB avg_probs partial (swizzled)
    __shared__ float sred[8];
    __shared__ float ssum[8], usum[8];
    __shared__ float sm_bc, ssinv_bc;
    __shared__ int   scnt;
    __shared__ int   scand[CAND];
    int tid = threadIdx.x, lane = tid & 31, wid = tid >> 5;

    #pragma unroll
    for (int j = 0; j < 32; j++) ap[j * 256 + tid] = 0.f;   // ownership: index ≡ tid (mod 256)

    int n0 = blockIdx.x * SROWS;
    uint4 v[4];
    {
        const uint4* rp = (const uint4*)(g_L + (size_t)n0 * KC);
        #pragma unroll
        for (int j = 0; j < 4; j++) v[j] = rp[j * 256 + tid];
    }

    for (int r = 0; r < SROWS; r++) {
        int n = n0 + r;

        float lv[4][8];
        float best = -INFINITY;
        #pragma unroll
        for (int j = 0; j < 4; j++) {
            lv[j][0] = bf2f(v[j].x & 0xffff); lv[j][1] = bf2f(v[j].x >> 16);
            lv[j][2] = bf2f(v[j].y & 0xffff); lv[j][3] = bf2f(v[j].y >> 16);
            lv[j][4] = bf2f(v[j].z & 0xffff); lv[j][5] = bf2f(v[j].z >> 16);
            lv[j][6] = bf2f(v[j].w & 0xffff); lv[j][7] = bf2f(v[j].w >> 16);
            #pragma unroll
            for (int i = 0; i < 8; i++) best = fmaxf(best, lv[j][i]);
        }
        if (r + 1 < SROWS) {            // prefetch next row: hides DRAM behind this row's work
            const uint4* rp = (const uint4*)(g_L + (size_t)(n + 1) * KC);
            #pragma unroll
            for (int j = 0; j < 4; j++) v[j] = rp[j * 256 + tid];
        }
        #pragma unroll
        for (int o = 16; o; o >>= 1) best = fmaxf(best, __shfl_xor_sync(0xffffffff, best, o));
        if (lane == 0) sred[wid] = best;
        __syncthreads();
        if (tid == 0) {
            float m = -INFINITY;
            #pragma unroll
            for (int w = 0; w < 8; w++) m = fmaxf(m, sred[w]);
            sm_bc = m; scnt = 0;
        }
        __syncthreads();
        float m = sm_bc;
        float thr = m - WWIN;

        float s = 0.f, u = 0.f;
        #pragma unroll
        for (int j = 0; j < 4; j++)
            #pragma unroll
            for (int i = 0; i < 8; i++) {
                float l = lv[j][i];
                float z = l - m;
                float e = __expf(z);
                s += e; u += z * e;
                if (l > thr) {
                    int pos = atomicAdd(&scnt, 1);
                    if (pos < CAND) scand[pos] = (j * 256 + tid) * 8 + i;
                }
                lv[j][i] = e;           // reuse registers: exp values
            }
        #pragma unroll
        for (int o = 16; o; o >>= 1) {
            s += __shfl_xor_sync(0xffffffff, s, o);
            u += __shfl_xor_sync(0xffffffff, u, o);
        }
        if (lane == 0) { ssum[wid] = s; usum[wid] = u; }
        __syncthreads();
        if (tid == 0) {
            float S = 0.f, U = 0.f;
            #pragma unroll
            for (int w = 0; w < 8; w++) { S += ssum[w]; U += usum[w]; }
            float sinv = 1.f / S;
            ssinv_bc = sinv;
            g_ccnt[n] = scnt;
            atomicAdd(&g_plogp, U * sinv - logf(S));
        }
        __syncthreads();
        float sinv = ssinv_bc;
        int cc = min(scnt, CAND);
        if (tid < cc) g_cand[(size_t)n * CAND + tid] = scand[tid];

        // ap[(k&7)*1024 + k>>3] with k=(j*256+tid)*8+i  ->  addr = i*1024 + j*256 + tid
        #pragma unroll
        for (int j = 0; j < 4; j++)
            #pragma unroll
            for (int i = 0; i < 8; i++)
                ap[i * 1024 + j * 256 + tid] += lv[j][i] * sinv;
        __syncthreads();   // protect scand/scnt across rows
    }

    // atomic-free flush: private partial row (deswizzled, coalesced)
    float* dst = g_avgp_p[blockIdx.x];
    for (int k = tid; k < KC; k += 256)
        dst[k] = ap[(k & 7) * 1024 + (k >> 3)];
}

// ---------------- fused: exact argmin (fp64) + gather + MSE + index out ----------------
__global__ __launch_bounds__(256) void refine_gather_kernel(const float* __restrict__ x,
                                                            const float* __restrict__ cb,
                                                            float* __restrict__ out) {
    __shared__ float xs[DD];
    __shared__ double a2s;
    __shared__ double cdist[CAND];
    __shared__ int    ckey[CAND];
    __shared__ double rvd[256];
    __shared__ float  rv[256];
    __shared__ int    ri[256];
    __shared__ int    sbk;
    int n = blockIdx.x, tid = threadIdx.x;
    int lane = tid & 31, w = tid >> 5;

    xs[tid] = x[(size_t)n * DD + tid];
    rvd[tid] = (double)xs[tid] * (double)xs[tid];
    __syncthreads();
    for (int off = 128; off; off >>= 1) {
        if (tid < off) rvd[tid] += rvd[tid + off];
        __syncthreads();
    }
    if (tid == 0) a2s = rvd[0];
    __syncthreads();
    double a2 = a2s;
    int cnt = g_ccnt[n];

    if (cnt <= CAND) {
        for (int ci = w; ci < cnt; ci += 8) {
            int k = g_cand[(size_t)n * CAND + ci];
            const float* c = cb + (size_t)k * DD;
            double dot = 0.0;
            #pragma unroll
            for (int d = lane; d < DD; d += 32) dot += (double)xs[d] * (double)c[d];
            #pragma unroll
            for (int o = 16; o; o >>= 1) dot += __shfl_down_sync(0xffffffff, dot, o);
            if (lane == 0) { cdist[ci] = a2 - 2.0 * dot + (double)g_c2[k]; ckey[ci] = k; }
        }
        __syncthreads();
        if (tid == 0) {
            double bd = INFINITY; int bk = KC;
            for (int ci = 0; ci < cnt; ci++) {
                double d = cdist[ci]; int k = ckey[ci];
                if (d < bd || (d == bd && k < bk)) { bd = d; bk = k; }
            }
            sbk = bk;
        }
    } else {
        float bdist = INFINITY; int bk = KC;
        float a2f = (float)a2;
        for (int k = tid; k < KC; k += 256) {
            const float* c = cb + (size_t)k * DD;
            float dot = 0.f;
            #pragma unroll 8
            for (int d = 0; d < DD; d += 4) {
                float4 cc = *(const float4*)(c + d);
                dot += xs[d] * cc.x + xs[d+1] * cc.y + xs[d+2] * cc.z + xs[d+3] * cc.w;
            }
            float dist = a2f - 2.f * dot + g_c2[k];
            if (dist < bdist) { bdist = dist; bk = k; }
        }
        rv[tid] = bdist; ri[tid] = bk;
        __syncthreads();
        for (int off = 128; off; off >>= 1) {
            if (tid < off) {
                float ov = rv[tid + off]; int oi = ri[tid + off];
                if (ov < rv[tid] || (ov == rv[tid] && oi < ri[tid])) { rv[tid] = ov; ri[tid] = oi; }
            }
            __syncthreads();
        }
        if (tid == 0) sbk = ri[0];
    }
    __syncthreads();
    int idx = sbk;

    // gather + MSE + outputs
    float q  = cb[(size_t)idx * DD + tid];
    out[(size_t)n * DD + tid] = q;
    float d = q - xs[tid];
    float sq = d * d;
    #pragma unroll
    for (int o = 16; o; o >>= 1) sq += __shfl_down_sync(0xffffffff, sq, o);
    rv[tid] = (lane == 0) ? sq : 0.f;
    __syncthreads();
    if (tid == 0) {
        float t = 0.f;
        #pragma unroll
        for (int ww = 0; ww < 8; ww++) t += rv[ww * 32];
        atomicAdd(&g_mse, t);
        out[(size_t)TOTAL_Q + 1 + n] = (float)idx;
    }
}

// ---------------- avg entropy: reduce 1024 partials per column ----------------
__global__ __launch_bounds__(256) void avgent_kernel() {
    int k = blockIdx.x * blockDim.x + threadIdx.x;
    float sum = 0.f;
    #pragma unroll 4
    for (int b = 0; b < NBLK; b++) sum += g_avgp_p[b][k];
    float ap = sum * (1.f / (float)NROWS);
    float h = -ap * logf(ap + 1e-5f);
    #pragma unroll
    for (int o = 16; o; o >>= 1) h += __shfl_down_sync(0xffffffff, h, o);
    __shared__ float sh[8];
    int wid = threadIdx.x >> 5, lid = threadIdx.x & 31;
    if (lid == 0) sh[wid] = h;
    __syncthreads();
    if (threadIdx.x == 0) {
        float t = 0.f;
        #pragma unroll
        for (int w = 0; w < 8; w++) t += sh[w];
        atomicAdd(&g_avgent, t);
    }
}

// ---------------- final loss ----------------
__global__ void final_kernel(float* __restrict__ out) {
    float mse_mean = g_mse / (float)TOTAL_Q;
    float sample_entropy = -g_plogp / (float)NROWS;
    float entropy_loss = sample_entropy - g_avgent;
    float loss = 1.25f * mse_mean + 0.1f * entropy_loss;
    out[TOTAL_Q] = loss;
}

extern "C" void kernel_launch(void* const* d_in, const int* in_sizes, int n_in,
                              void* d_out, int out_size) {
    const float* x  = (const float*)d_in[0];
    const float* cb = (const float*)d_in[1];
    float* out = (float*)d_out;

    cudaFuncSetAttribute(mma_gemm_kernel, cudaFuncAttributeMaxDynamicSharedMemorySize, GSMEM);

    init_kernel<<<1, 32>>>();
    c2_kernel<<<KC, 256>>>(cb);
    convert_kernel<<<TOTAL_Q / 1024, 256>>>(x, cb);
    mma_gemm_kernel<<<dim3(KC / BN, NROWS / BM), 256, GSMEM>>>();
    stats_kernel<<<NBLK, 256>>>();
    avgent_kernel<<<KC / 256, 256>>>();
    refine_gather_kernel<<<NROWS, 256>>>(x, cb, out);
    final_kernel<<<1, 1>>>(out);
}

// round 16
// speedup vs baseline: 1.4331x; 1.4331x over previous
#include <cuda_runtime.h>
#include <cuda_bf16.h>
#include <math.h>
#include <stdint.h>

#define NROWS 8192
#define KC    8192
#define DD    256
#define TOTAL_Q (NROWS*DD)
#define CAND  128
#define WWIN  32.0f          // candidate logit window (>= 2*E_hard)

// ---------------- scratch ----------------
__device__ __nv_bfloat16 g_L[(size_t)NROWS * KC];    // 128 MB: bf16 logits
__device__ __nv_bfloat16 g_A[(size_t)NROWS * DD];
__device__ __nv_bfloat16 g_B[(size_t)KC * DD];
__device__ float g_c2[KC];
__device__ int   g_ccnt[NROWS];
__device__ int   g_cand[(size_t)NROWS * CAND];
__device__ float g_avgp[KC];
__device__ float g_plogp;
__device__ float g_avgent;
__device__ float g_mse;

__device__ __forceinline__ float bf2f(uint32_t lo16) {
    uint32_t u = lo16 << 16;
    return __uint_as_float(u);
}
__device__ __forceinline__ uint32_t pack2(float a, float b) {
    __nv_bfloat162 t = __floats2bfloat162_rn(a, b);
    return reinterpret_cast<uint32_t&>(t);
}

// ---------------- init ----------------
__global__ void init_kernel() {
    int i = blockIdx.x * blockDim.x + threadIdx.x;
    if (i < KC) g_avgp[i] = 0.f;
    if (i == 0) { g_plogp = 0.f; g_avgent = 0.f; g_mse = 0.f; }
}

// ---------------- |c_k|^2 ----------------
__global__ __launch_bounds__(256) void c2_kernel(const float* __restrict__ cb) {
    int k = blockIdx.x;
    float v = cb[(size_t)k * DD + threadIdx.x];
    float sq = v * v;
    #pragma unroll
    for (int o = 16; o; o >>= 1) sq += __shfl_down_sync(0xffffffff, sq, o);
    __shared__ float sh[8];
    int wid = threadIdx.x >> 5, lid = threadIdx.x & 31;
    if (lid == 0) sh[wid] = sq;
    __syncthreads();
    if (threadIdx.x == 0) {
        float t = 0.f;
        #pragma unroll
        for (int w = 0; w < 8; w++) t += sh[w];
        g_c2[k] = t;
    }
}

// ---------------- fp32 -> bf16 ----------------
__global__ __launch_bounds__(256) void convert_kernel(const float* __restrict__ x,
                                                      const float* __restrict__ cb) {
    int i = (blockIdx.x * 256 + threadIdx.x) * 4;
    {
        float4 v = *(const float4*)(x + i);
        *(uint2*)(g_A + i) = make_uint2(pack2(v.x, v.y), pack2(v.z, v.w));
    }
    {
        float4 v = *(const float4*)(cb + i);
        *(uint2*)(g_B + i) = make_uint2(pack2(v.x, v.y), pack2(v.z, v.w));
    }
}

// ---------------- bf16 mma GEMM: 128x128 tile, 64x32 warps, 4-stage, 2 CTAs/SM ----------------
#define BM 128
#define BN 128
#define BK 32
#define PAD 40
#define TILE_E (128*PAD)
#define TILE_B (TILE_E*2)      // 10240 bytes
#define STAGE_B (TILE_B*2)     // 20480 bytes
#define NSTAGE 4
#define GSMEM (NSTAGE*STAGE_B) // 81920
#define NIT (DD/BK)            // 8

__device__ __forceinline__ void mma16816(float* d, const uint32_t* a, const uint32_t* b) {
    asm volatile("mma.sync.aligned.m16n8k16.row.col.f32.bf16.bf16.f32 "
        "{%0,%1,%2,%3}, {%4,%5,%6,%7}, {%8,%9}, {%0,%1,%2,%3};"
        : "+f"(d[0]), "+f"(d[1]), "+f"(d[2]), "+f"(d[3])
        : "r"(a[0]), "r"(a[1]), "r"(a[2]), "r"(a[3]), "r"(b[0]), "r"(b[1]));
}
__device__ __forceinline__ void ldsm4(uint32_t* r, uint32_t addr) {
    asm volatile("ldmatrix.sync.aligned.m8n8.x4.shared.b16 {%0,%1,%2,%3}, [%4];"
        : "=r"(r[0]), "=r"(r[1]), "=r"(r[2]), "=r"(r[3]) : "r"(addr));
}

__global__ __launch_bounds__(256, 2) void mma_gemm_kernel() {
    extern __shared__ __align__(16) char dsm[];
    int tid = threadIdx.x, lane = tid & 31, wid = tid >> 5;
    int warpM = wid & 1, warpN = wid >> 1;       // 2 x 4 warps, each 64x32
    int row0 = blockIdx.y * BM, col0 = blockIdx.x * BN;

    const __nv_bfloat16* Ag = g_A + (size_t)row0 * DD;
    const __nv_bfloat16* Bg = g_B + (size_t)col0 * DD;
    uint32_t sbase = (uint32_t)__cvta_generic_to_shared(dsm);

    int lr0 = (tid + 0)   >> 2, ls0 = (tid + 0)   & 3;
    int lr1 = (tid + 256) >> 2, ls1 = (tid + 256) & 3;
    uint32_t so0 = (uint32_t)(lr0 * PAD + ls0 * 8) * 2;
    uint32_t so1 = (uint32_t)(lr1 * PAD + ls1 * 8) * 2;

    // cp.async.cg: L2-only, keep L1TEX bandwidth for ldmatrix (measured good in R14)
    #define LOAD_STAGE(stage, kc) do { \
        uint32_t ab = sbase + (stage) * STAGE_B; \
        uint32_t bb = ab + TILE_B; \
        asm volatile("cp.async.cg.shared.global [%0], [%1], 16;" :: "r"(ab + so0), "l"(Ag + (size_t)lr0 * DD + (kc) + ls0 * 8)); \
        asm volatile("cp.async.cg.shared.global [%0], [%1], 16;" :: "r"(ab + so1), "l"(Ag + (size_t)lr1 * DD + (kc) + ls1 * 8)); \
        asm volatile("cp.async.cg.shared.global [%0], [%1], 16;" :: "r"(bb + so0), "l"(Bg + (size_t)lr0 * DD + (kc) + ls0 * 8)); \
        asm volatile("cp.async.cg.shared.global [%0], [%1], 16;" :: "r"(bb + so1), "l"(Bg + (size_t)lr1 * DD + (kc) + ls1 * 8)); \
        asm volatile("cp.async.commit_group;"); \
    } while (0)

    int lrow = ((lane >> 3) & 1) * 8 + (lane & 7);
    int lkof = (lane >> 4) * 8;
    uint32_t aoff = (uint32_t)((warpM * 64 + lrow) * PAD + lkof) * 2;
    uint32_t boff = (uint32_t)((warpN * 32 + lrow) * PAD + lkof) * 2;

    float acc[4][4][4];
    #pragma unroll
    for (int mt = 0; mt < 4; mt++)
        #pragma unroll
        for (int nt = 0; nt < 4; nt++)
            #pragma unroll
            for (int j = 0; j < 4; j++) acc[mt][nt][j] = 0.f;

    LOAD_STAGE(0, 0);
    LOAD_STAGE(1, BK);
    LOAD_STAGE(2, 2 * BK);

    int stage = 0;
    for (int it = 0; it < NIT; it++) {
        asm volatile("cp.async.wait_group 2;");
        __syncthreads();

        uint32_t bufA = sbase + stage * STAGE_B;
        uint32_t bufB = bufA + TILE_B;
        #pragma unroll
        for (int ks = 0; ks < 2; ks++) {
            uint32_t kst = ks * 16 * 2;
            uint32_t aF[4][4];
            #pragma unroll
            for (int mt = 0; mt < 4; mt++)
                ldsm4(aF[mt], bufA + aoff + mt * (16 * PAD * 2) + kst);
            uint32_t bF[4][2];
            #pragma unroll
            for (int p = 0; p < 2; p++) {
                uint32_t r[4];
                ldsm4(r, bufB + boff + p * (16 * PAD * 2) + kst);
                bF[2*p][0] = r[0]; bF[2*p][1] = r[2];
                bF[2*p+1][0] = r[1]; bF[2*p+1][1] = r[3];
            }
            #pragma unroll
            for (int mt = 0; mt < 4; mt++)
                #pragma unroll
                for (int nt = 0; nt < 4; nt++)
                    mma16816(acc[mt][nt], aF[mt], bF[nt]);
        }

        if (it + 3 < NIT) {
            int ns = (stage + 3) % NSTAGE;
            LOAD_STAGE(ns, (it + 3) * BK);
        } else {
            asm volatile("cp.async.commit_group;");
        }
        stage = (stage + 1) % NSTAGE;
    }

    // epilogue: logit = 200*G - 100*c2, store bf16
    int mr = row0 + warpM * 64 + (lane >> 2);
    int nc = col0 + warpN * 32 + (lane & 3) * 2;
    #pragma unroll
    for (int nt = 0; nt < 4; nt++) {
        int c = nc + nt * 8;
        float c2a = g_c2[c] * 100.f, c2b = g_c2[c + 1] * 100.f;
        #pragma unroll
        for (int mt = 0; mt < 4; mt++) {
            float* d = acc[mt][nt];
            size_t o0 = ((size_t)(mr + mt * 16) * KC + c) >> 1;
            size_t o1 = ((size_t)(mr + mt * 16 + 8) * KC + c) >> 1;
            ((uint32_t*)g_L)[o0] = pack2(d[0] * 200.f - c2a, d[1] * 200.f - c2b);
            ((uint32_t*)g_L)[o1] = pack2(d[2] * 200.f - c2a, d[3] * 200.f - c2b);
        }
    }
}

// ---------------- register-resident stats (round-13 measured version) ----------------
// ap swizzle: logical k stored at (k&7)*1024 + (k>>3) — thread-private (all ≡ tid mod 256)
#define SROWS 8
__global__ __launch_bounds__(256) void stats_kernel() {
    __shared__ float ap[KC];          // 32 KB avg_probs partial (swizzled)
    __shared__ float sred[8];
    __shared__ float ssum[8], usum[8];
    __shared__ float sm_bc, ssinv_bc;
    __shared__ int   scnt;
    __shared__ int   scand[CAND];
    int tid = threadIdx.x, lane = tid & 31, wid = tid >> 5;

    #pragma unroll
    for (int j = 0; j < 32; j++) ap[j * 256 + tid] = 0.f;   // ownership: index ≡ tid (mod 256)

    for (int r = 0; r < SROWS; r++) {
        int n = blockIdx.x * SROWS + r;
        const uint4* rp = (const uint4*)(g_L + (size_t)n * KC);

        float lv[4][8];
        float best = -INFINITY;
        #pragma unroll
        for (int j = 0; j < 4; j++) {
            uint4 v = rp[j * 256 + tid];
            lv[j][0] = bf2f(v.x & 0xffff); lv[j][1] = bf2f(v.x >> 16);
            lv[j][2] = bf2f(v.y & 0xffff); lv[j][3] = bf2f(v.y >> 16);
            lv[j][4] = bf2f(v.z & 0xffff); lv[j][5] = bf2f(v.z >> 16);
            lv[j][6] = bf2f(v.w & 0xffff); lv[j][7] = bf2f(v.w >> 16);
            #pragma unroll
            for (int i = 0; i < 8; i++) best = fmaxf(best, lv[j][i]);
        }
        #pragma unroll
        for (int o = 16; o; o >>= 1) best = fmaxf(best, __shfl_xor_sync(0xffffffff, best, o));
        if (lane == 0) sred[wid] = best;
        __syncthreads();
        if (tid == 0) {
            float m = -INFINITY;
            #pragma unroll
            for (int w = 0; w < 8; w++) m = fmaxf(m, sred[w]);
            sm_bc = m; scnt = 0;
        }
        __syncthreads();
        float m = sm_bc;
        float thr = m - WWIN;

        float s = 0.f, u = 0.f;
        #pragma unroll
        for (int j = 0; j < 4; j++)
            #pragma unroll
            for (int i = 0; i < 8; i++) {
                float l = lv[j][i];
                float z = l - m;
                float e = __expf(z);
                s += e; u += z * e;
                if (l > thr) {
                    int pos = atomicAdd(&scnt, 1);
                    if (pos < CAND) scand[pos] = (j * 256 + tid) * 8 + i;
                }
                lv[j][i] = e;           // reuse registers: exp values
            }
        #pragma unroll
        for (int o = 16; o; o >>= 1) {
            s += __shfl_xor_sync(0xffffffff, s, o);
            u += __shfl_xor_sync(0xffffffff, u, o);
        }
        if (lane == 0) { ssum[wid] = s; usum[wid] = u; }
        __syncthreads();
        if (tid == 0) {
            float S = 0.f, U = 0.f;
            #pragma unroll
            for (int w = 0; w < 8; w++) { S += ssum[w]; U += usum[w]; }
            float sinv = 1.f / S;
            ssinv_bc = sinv;
            g_ccnt[n] = scnt;
            atomicAdd(&g_plogp, U * sinv - logf(S));
        }
        __syncthreads();
        float sinv = ssinv_bc;
        int cc = min(scnt, CAND);
        if (tid < cc) g_cand[(size_t)n * CAND + tid] = scand[tid];

        // ap[(k&7)*1024 + k>>3] with k=(j*256+tid)*8+i  ->  addr = i*1024 + j*256 + tid
        #pragma unroll
        for (int j = 0; j < 4; j++)
            #pragma unroll
            for (int i = 0; i < 8; i++)
                ap[i * 1024 + j * 256 + tid] += lv[j][i] * sinv;
        __syncthreads();   // protect scand/scnt across rows
    }

    for (int k = tid; k < KC; k += 256)
        atomicAdd(&g_avgp[k], ap[(k & 7) * 1024 + (k >> 3)]);
}

// ---------------- fused: exact argmin (fp64) + gather + MSE + index out ----------------
__global__ __launch_bounds__(256) void refine_gather_kernel(const float* __restrict__ x,
                                                            const float* __restrict__ cb,
                                                            float* __restrict__ out) {
    __shared__ float xs[DD];
    __shared__ double a2s;
    __shared__ double cdist[CAND];
    __shared__ int    ckey[CAND];
    __shared__ double rvd[256];
    __shared__ float  rv[256];
    __shared__ int    ri[256];
    __shared__ int    sbk;
    int n = blockIdx.x, tid = threadIdx.x;
    int lane = tid & 31, w = tid >> 5;

    xs[tid] = x[(size_t)n * DD + tid];
    rvd[tid] = (double)xs[tid] * (double)xs[tid];
    __syncthreads();
    for (int off = 128; off; off >>= 1) {
        if (tid < off) rvd[tid] += rvd[tid + off];
        __syncthreads();
    }
    if (tid == 0) a2s = rvd[0];
    __syncthreads();
    double a2 = a2s;
    int cnt = g_ccnt[n];

    if (cnt <= CAND) {
        for (int ci = w; ci < cnt; ci += 8) {
            int k = g_cand[(size_t)n * CAND + ci];
            const float* c = cb + (size_t)k * DD;
            double dot = 0.0;
            #pragma unroll
            for (int d = lane; d < DD; d += 32) dot += (double)xs[d] * (double)c[d];
            #pragma unroll
            for (int o = 16; o; o >>= 1) dot += __shfl_down_sync(0xffffffff, dot, o);
            if (lane == 0) { cdist[ci] = a2 - 2.0 * dot + (double)g_c2[k]; ckey[ci] = k; }
        }
        __syncthreads();
        if (tid == 0) {
            double bd = INFINITY; int bk = KC;
            for (int ci = 0; ci < cnt; ci++) {
                double d = cdist[ci]; int k = ckey[ci];
                if (d < bd || (d == bd && k < bk)) { bd = d; bk = k; }
            }
            sbk = bk;
        }
    } else {
        float bdist = INFINITY; int bk = KC;
        float a2f = (float)a2;
        for (int k = tid; k < KC; k += 256) {
            const float* c = cb + (size_t)k * DD;
            float dot = 0.f;
            #pragma unroll 8
            for (int d = 0; d < DD; d += 4) {
                float4 cc = *(const float4*)(c + d);
                dot += xs[d] * cc.x + xs[d+1] * cc.y + xs[d+2] * cc.z + xs[d+3] * cc.w;
            }
            float dist = a2f - 2.f * dot + g_c2[k];
            if (dist < bdist) { bdist = dist; bk = k; }
        }
        rv[tid] = bdist; ri[tid] = bk;
        __syncthreads();
        for (int off = 128; off; off >>= 1) {
            if (tid < off) {
                float ov = rv[tid + off]; int oi = ri[tid + off];
                if (ov < rv[tid] || (ov == rv[tid] && oi < ri[tid])) { rv[tid] = ov; ri[tid] = oi; }
            }
            __syncthreads();
        }
        if (tid == 0) sbk = ri[0];
    }
    __syncthreads();
    int idx = sbk;

    // gather + MSE + outputs
    float q  = cb[(size_t)idx * DD + tid];
    out[(size_t)n * DD + tid] = q;
    float d = q - xs[tid];
    float sq = d * d;
    #pragma unroll
    for (int o = 16; o; o >>= 1) sq += __shfl_down_sync(0xffffffff, sq, o);
    rv[tid] = (lane == 0) ? sq : 0.f;
    __syncthreads();
    if (tid == 0) {
        float t = 0.f;
        #pragma unroll
        for (int ww = 0; ww < 8; ww++) t += rv[ww * 32];
        atomicAdd(&g_mse, t);
        out[(size_t)TOTAL_Q + 1 + n] = (float)idx;
    }
}

// ---------------- avg entropy ----------------
__global__ __launch_bounds__(256) void avgent_kernel() {
    int i = blockIdx.x * blockDim.x + threadIdx.x;
    float ap = g_avgp[i] * (1.f / (float)NROWS);
    float h = -ap * logf(ap + 1e-5f);
    #pragma unroll
    for (int o = 16; o; o >>= 1) h += __shfl_down_sync(0xffffffff, h, o);
    __shared__ float sh[8];
    int wid = threadIdx.x >> 5, lid = threadIdx.x & 31;
    if (lid == 0) sh[wid] = h;
    __syncthreads();
    if (threadIdx.x == 0) {
        float t = 0.f;
        #pragma unroll
        for (int w = 0; w < 8; w++) t += sh[w];
        atomicAdd(&g_avgent, t);
    }
}

// ---------------- final loss ----------------
__global__ void final_kernel(float* __restrict__ out) {
    float mse_mean = g_mse / (float)TOTAL_Q;
    float sample_entropy = -g_plogp / (float)NROWS;
    float entropy_loss = sample_entropy - g_avgent;
    float loss = 1.25f * mse_mean + 0.1f * entropy_loss;
    out[TOTAL_Q] = loss;
}

extern "C" void kernel_launch(void* const* d_in, const int* in_sizes, int n_in,
                              void* d_out, int out_size) {
    const float* x  = (const float*)d_in[0];
    const float* cb = (const float*)d_in[1];
    float* out = (float*)d_out;

    cudaFuncSetAttribute(mma_gemm_kernel, cudaFuncAttributeMaxDynamicSharedMemorySize, GSMEM);

    init_kernel<<<32, 256>>>();
    c2_kernel<<<KC, 256>>>(cb);
    convert_kernel<<<TOTAL_Q / 1024, 256>>>(x, cb);
    mma_gemm_kernel<<<dim3(KC / BN, NROWS / BM), 256, GSMEM>>>();
    stats_kernel<<<NROWS / SROWS, 256>>>();
    avgent_kernel<<<KC / 256, 256>>>();
    refine_gather_kernel<<<NROWS, 256>>>(x, cb, out);
    final_kernel<<<1, 1>>>(out);
}